// round 2
// baseline (speedup 1.0000x reference)
#include <cuda_runtime.h>
#include <cstdint>
#include <cfloat>

// Problem constants
#define B_    64
#define N_    512
#define BN_   32768          // B_*N_
#define K_    8
#define H_    336            // hidden dim of edge MLPs
#define C_    256            // conv output dim
#define CAT_  1030           // 6 + 4*256

// ---------------- scratch (static device memory; no runtime allocation) ----------------
__device__ float g_xo[4 * BN_ * C_];              // conv outputs x1..x4
__device__ float g_dist[(size_t)B_ * N_ * N_];    // pairwise distances
__device__ int   g_knn[BN_ * K_];                 // global neighbor indices
__device__ float g_ab[(size_t)BN_ * 672];         // per-node a (0..335) and b (336..671)
__device__ float g_wcomb[256 * 672];              // combined first-linear weights
__device__ float g_bcomb[672];
__device__ float g_h1[(size_t)BN_ * K_ * H_];     // per-edge hidden
__device__ float g_h2[(size_t)BN_ * K_ * C_];     // per-edge output
__device__ float g_cat[(size_t)BN_ * CAT_];       // concat features
__device__ float g_t[(size_t)BN_ * H_];           // mlp1 hidden
__device__ float g_m[(size_t)BN_ * C_];           // mlp1 output per node
__device__ float g_norm[BN_];
__device__ float g_pool[B_ * C_];

__device__ __forceinline__ float lrelu(float v) { return v >= 0.f ? v : 0.01f * v; }

// ---------------- kernels ----------------

__global__ void norm_kernel(const float* __restrict__ x, float* __restrict__ nrm, int F) {
    int i = blockIdx.x * blockDim.x + threadIdx.x;
    if (i >= BN_) return;
    const float* r = x + (size_t)i * F;
    float s = 0.f;
    for (int f = 0; f < F; ++f) { float v = r[f]; s += v * v; }
    nrm[i] = s;
}

// Batched distance GEMM: D[b][i][j] = |xi|^2 + |xj|^2 - 2 xi.xj
__global__ void dist_kernel(const float* __restrict__ X, const float* __restrict__ nrm,
                            float* __restrict__ D, int F) {
    __shared__ float sI[16][68];
    __shared__ float sJ[16][68];
    int b = blockIdx.z;
    int i0 = blockIdx.y * 64, j0 = blockIdx.x * 64;
    int base = b * N_;
    int tid = threadIdx.x;
    int tx = tid & 15, ty = tid >> 4;
    float acc[4][4] = {};
    for (int k0 = 0; k0 < F; k0 += 16) {
        int kk = tid & 15, mm = tid >> 4;
#pragma unroll
        for (int q = 0; q < 4; ++q) {
            int m = mm + q * 16;
            float vi = 0.f, vj = 0.f;
            if (k0 + kk < F) {
                vi = X[(size_t)(base + i0 + m) * F + k0 + kk];
                vj = X[(size_t)(base + j0 + m) * F + k0 + kk];
            }
            sI[kk][m] = vi;
            sJ[kk][m] = vj;
        }
        __syncthreads();
#pragma unroll
        for (int k = 0; k < 16; ++k) {
            float4 a4 = *reinterpret_cast<const float4*>(&sI[k][ty * 4]);
            float4 b4 = *reinterpret_cast<const float4*>(&sJ[k][tx * 4]);
            float ar[4] = {a4.x, a4.y, a4.z, a4.w};
            float br[4] = {b4.x, b4.y, b4.z, b4.w};
#pragma unroll
            for (int r = 0; r < 4; ++r)
#pragma unroll
                for (int c = 0; c < 4; ++c) acc[r][c] += ar[r] * br[c];
        }
        __syncthreads();
    }
#pragma unroll
    for (int r = 0; r < 4; ++r) {
        int i = i0 + ty * 4 + r;
        float ni = nrm[base + i];
        int j = j0 + tx * 4;
        float4 o;
        o.x = ni + nrm[base + j + 0] - 2.f * acc[r][0];
        o.y = ni + nrm[base + j + 1] - 2.f * acc[r][1];
        o.z = ni + nrm[base + j + 2] - 2.f * acc[r][2];
        o.w = ni + nrm[base + j + 3] - 2.f * acc[r][3];
        *reinterpret_cast<float4*>(&D[(size_t)(base + i) * N_ + j]) = o;
    }
}

// Top-8 smallest distances per row; ties -> smaller index (matches jax.lax.top_k stability).
__global__ void topk_kernel(const float* __restrict__ D, int* __restrict__ knn) {
    int gid = blockIdx.x * blockDim.x + threadIdx.x;
    if (gid >= BN_) return;
    const float* row = D + (size_t)gid * N_;
    float kd[K_];
    int ki[K_];
#pragma unroll
    for (int k = 0; k < K_; ++k) { kd[k] = FLT_MAX; ki[k] = -1; }
    for (int j = 0; j < N_; ++j) {
        float d = row[j];
        if (d < kd[K_ - 1]) {
            int p = K_ - 1;
            while (p > 0 && kd[p - 1] > d) { kd[p] = kd[p - 1]; ki[p] = ki[p - 1]; --p; }
            kd[p] = d;
            ki[p] = j;
        }
    }
    int b = gid / N_;
#pragma unroll
    for (int k = 0; k < K_; ++k) knn[gid * K_ + k] = b * N_ + ki[k];
}

// Combined first-linear weights: cols 0..335 = w1_top - w1_bot, cols 336..671 = w1_bot.
__global__ void prep_kernel(const float* __restrict__ w1, const float* __restrict__ b1,
                            float* __restrict__ wcomb, float* __restrict__ bcomb, int F) {
    int idx = blockIdx.x * blockDim.x + threadIdx.x;
    if (idx < 672) bcomb[idx] = (idx < H_) ? b1[idx] : 0.f;
    int total = F * 672;
    if (idx >= total) return;
    int f = idx / 672, h = idx % 672;
    float v;
    if (h < H_) v = w1[f * H_ + h] - w1[(F + f) * H_ + h];
    else        v = w1[(F + f) * H_ + (h - H_)];
    wcomb[idx] = v;
}

// Generic SGEMM: C = act(A[M,K] @ W[K,N] + bias). 64x64 tile, 4x4 per thread.
template <int ACT>
__global__ void gemm_kernel(const float* __restrict__ A, const float* __restrict__ W,
                            const float* __restrict__ bias, float* __restrict__ Cc,
                            int M, int Kd, int Nd) {
    __shared__ float sA[16][68];
    __shared__ float sW[16][68];
    int m0 = blockIdx.y * 64, n0 = blockIdx.x * 64;
    int tid = threadIdx.x;
    int tx = tid & 15, ty = tid >> 4;
    float acc[4][4] = {};
    for (int k0 = 0; k0 < Kd; k0 += 16) {
        {
            int kk = tid & 15, mm = tid >> 4;
#pragma unroll
            for (int q = 0; q < 4; ++q) {
                int m = mm + q * 16;
                sA[kk][m] = (k0 + kk < Kd) ? A[(size_t)(m0 + m) * Kd + k0 + kk] : 0.f;
            }
        }
        {
            int nn = tid & 63, kq = tid >> 6;
#pragma unroll
            for (int q = 0; q < 4; ++q) {
                int k = kq + q * 4;
                sW[k][nn] = (k0 + k < Kd && n0 + nn < Nd) ? W[(size_t)(k0 + k) * Nd + n0 + nn] : 0.f;
            }
        }
        __syncthreads();
#pragma unroll
        for (int k = 0; k < 16; ++k) {
            float4 a4 = *reinterpret_cast<const float4*>(&sA[k][ty * 4]);
            float4 b4 = *reinterpret_cast<const float4*>(&sW[k][tx * 4]);
            float ar[4] = {a4.x, a4.y, a4.z, a4.w};
            float br[4] = {b4.x, b4.y, b4.z, b4.w};
#pragma unroll
            for (int r = 0; r < 4; ++r)
#pragma unroll
                for (int c = 0; c < 4; ++c) acc[r][c] += ar[r] * br[c];
        }
        __syncthreads();
    }
#pragma unroll
    for (int r = 0; r < 4; ++r) {
        int m = m0 + ty * 4 + r;
#pragma unroll
        for (int c = 0; c < 4; ++c) {
            int n = n0 + tx * 4 + c;
            if (n < Nd) {
                float v = acc[r][c] + (bias ? bias[n] : 0.f);
                if (ACT) v = lrelu(v);
                Cc[(size_t)m * Nd + n] = v;
            }
        }
    }
}

// h1[e][s] = lrelu(a[i][s] + b[j][s]), vectorized by 4.
__global__ void h1_kernel(const float* __restrict__ ab, const int* __restrict__ knn,
                          float* __restrict__ h1) {
    int idx = blockIdx.x * blockDim.x + threadIdx.x;  // e*84 + s4
    int e = idx / 84, s4 = idx % 84;
    if (e >= BN_ * K_) return;
    int i = e >> 3;
    int j = knn[e];
    float4 a = *reinterpret_cast<const float4*>(&ab[(size_t)i * 672 + s4 * 4]);
    float4 b = *reinterpret_cast<const float4*>(&ab[(size_t)j * 672 + 336 + s4 * 4]);
    float4 o;
    o.x = lrelu(a.x + b.x);
    o.y = lrelu(a.y + b.y);
    o.z = lrelu(a.z + b.z);
    o.w = lrelu(a.w + b.w);
    *reinterpret_cast<float4*>(&h1[(size_t)e * H_ + s4 * 4]) = o;
}

__global__ void maxk_kernel(const float* __restrict__ h2, float* __restrict__ xo) {
    int idx = blockIdx.x * blockDim.x + threadIdx.x;
    if (idx >= BN_ * C_) return;
    int i = idx >> 8, c = idx & 255;
    float m = -FLT_MAX;
#pragma unroll
    for (int k = 0; k < K_; ++k) m = fmaxf(m, h2[(size_t)(i * K_ + k) * C_ + c]);
    xo[idx] = m;
}

__global__ void concat_kernel(const float* __restrict__ x, const float* __restrict__ x1,
                              const float* __restrict__ x2, const float* __restrict__ x3,
                              const float* __restrict__ x4, float* __restrict__ cat) {
    int idx = blockIdx.x * blockDim.x + threadIdx.x;
    if (idx >= BN_ * CAT_) return;
    int i = idx / CAT_, f = idx % CAT_;
    float v;
    if (f < 6) {
        v = x[i * 6 + f];
    } else {
        int g = f - 6;
        int l = g >> 8, c = g & 255;
        const float* src = (l == 0) ? x1 : (l == 1) ? x2 : (l == 2) ? x3 : x4;
        v = src[(size_t)i * C_ + c];
    }
    cat[idx] = v;
}

__global__ void pool_kernel(const float* __restrict__ m, float* __restrict__ g) {
    int b = blockIdx.x, c = threadIdx.x;  // 256 threads
    float s = 0.f;
    for (int n = 0; n < N_; ++n) s += m[(size_t)(b * N_ + n) * C_ + c];
    g[b * C_ + c] = s * (1.f / (float)N_);
}

// Final head: out = lrelu(g @ w1 + b1) @ w2 + b2 ; g:[64,256], w1:[256,128], w2:[128,3]
__global__ void head_kernel(const float* __restrict__ g, const float* __restrict__ w1,
                            const float* __restrict__ b1, const float* __restrict__ w2,
                            const float* __restrict__ b2, float* __restrict__ out) {
    __shared__ float sg[256];
    __shared__ float sh[128];
    int b = blockIdx.x, t = threadIdx.x;  // 128 threads
    sg[t] = g[b * 256 + t];
    sg[t + 128] = g[b * 256 + 128 + t];
    __syncthreads();
    float s = b1[t];
    for (int f = 0; f < 256; ++f) s += sg[f] * w1[f * 128 + t];
    sh[t] = lrelu(s);
    __syncthreads();
    if (t < 3) {
        float o = b2[t];
        for (int c = 0; c < 128; ++c) o += sh[c] * w2[c * 3 + t];
        out[b * 3 + t] = o;
    }
}

// ---------------- host ----------------
extern "C" void kernel_launch(void* const* d_in, const int* in_sizes, int n_in,
                              void* d_out, int out_size) {
    const float* x = (const float*)d_in[0];
    const float *cw1[4], *cb1[4], *cw2[4], *cb2[4];
    for (int L = 0; L < 4; ++L) {
        cw1[L] = (const float*)d_in[3 + 4 * L];
        cb1[L] = (const float*)d_in[4 + 4 * L];
        cw2[L] = (const float*)d_in[5 + 4 * L];
        cb2[L] = (const float*)d_in[6 + 4 * L];
    }
    const float* m1w1 = (const float*)d_in[19];
    const float* m1b1 = (const float*)d_in[20];
    const float* m1w2 = (const float*)d_in[21];
    const float* m1b2 = (const float*)d_in[22];
    const float* m2w1 = (const float*)d_in[23];
    const float* m2b1 = (const float*)d_in[24];
    const float* m2w2 = (const float*)d_in[25];
    const float* m2b2 = (const float*)d_in[26];
    float* out = (float*)d_out;

    float *p_xo, *p_d, *p_ab, *p_wc, *p_bc, *p_h1, *p_h2, *p_cat, *p_t, *p_m, *p_nrm, *p_pool;
    int* p_knn;
    cudaGetSymbolAddress((void**)&p_xo, g_xo);
    cudaGetSymbolAddress((void**)&p_d, g_dist);
    cudaGetSymbolAddress((void**)&p_knn, g_knn);
    cudaGetSymbolAddress((void**)&p_ab, g_ab);
    cudaGetSymbolAddress((void**)&p_wc, g_wcomb);
    cudaGetSymbolAddress((void**)&p_bc, g_bcomb);
    cudaGetSymbolAddress((void**)&p_h1, g_h1);
    cudaGetSymbolAddress((void**)&p_h2, g_h2);
    cudaGetSymbolAddress((void**)&p_cat, g_cat);
    cudaGetSymbolAddress((void**)&p_t, g_t);
    cudaGetSymbolAddress((void**)&p_m, g_m);
    cudaGetSymbolAddress((void**)&p_nrm, g_norm);
    cudaGetSymbolAddress((void**)&p_pool, g_pool);

    float* xL[4];
    for (int L = 0; L < 4; ++L) xL[L] = p_xo + (size_t)L * BN_ * C_;

    for (int L = 0; L < 4; ++L) {
        const float* xin = (L == 0) ? x : xL[L - 1];
        int F = (L == 0) ? 6 : C_;

        norm_kernel<<<BN_ / 256, 256>>>(xin, p_nrm, F);
        dist_kernel<<<dim3(8, 8, B_), 256>>>(xin, p_nrm, p_d, F);
        topk_kernel<<<BN_ / 256, 256>>>(p_d, p_knn);
        prep_kernel<<<(F * 672 + 255) / 256, 256>>>(cw1[L], cb1[L], p_wc, p_bc, F);
        // per-node a|b : [BN, F] @ [F, 672]
        gemm_kernel<0><<<dim3(11, BN_ / 64), 256>>>(xin, p_wc, p_bc, p_ab, BN_, F, 672);
        // per-edge hidden
        h1_kernel<<<(BN_ * K_ * 84) / 256, 256>>>(p_ab, p_knn, p_h1);
        // per-edge second linear: [BN*K, 336] @ [336, 256], lrelu
        gemm_kernel<1><<<dim3(4, (BN_ * K_) / 64), 256>>>(p_h1, cw2[L], cb2[L], p_h2,
                                                          BN_ * K_, H_, C_);
        maxk_kernel<<<(BN_ * C_) / 256, 256>>>(p_h2, xL[L]);
    }

    concat_kernel<<<(BN_ * CAT_ + 255) / 256, 256>>>(x, xL[0], xL[1], xL[2], xL[3], p_cat);
    gemm_kernel<1><<<dim3(6, BN_ / 64), 256>>>(p_cat, m1w1, m1b1, p_t, BN_, CAT_, H_);
    gemm_kernel<1><<<dim3(4, BN_ / 64), 256>>>(p_t, m1w2, m1b2, p_m, BN_, H_, C_);
    pool_kernel<<<B_, 256>>>(p_m, p_pool);
    head_kernel<<<B_, 128>>>(p_pool, m2w1, m2b1, m2w2, m2b2, out);
}

// round 3
// speedup vs baseline: 1.2017x; 1.2017x over previous
#include <cuda_runtime.h>
#include <cstdint>
#include <cfloat>

// Problem constants
#define B_    64
#define N_    512
#define BN_   32768          // B_*N_
#define K_    8
#define H_    336            // hidden dim of edge MLPs
#define C_    256            // conv output dim
#define CAT_  1030           // 6 + 4*256

// ---------------- scratch (static device memory; no runtime allocation) ----------------
__device__ float g_xo[4 * BN_ * C_];              // conv outputs x1..x4
__device__ float g_dist[(size_t)B_ * N_ * N_];    // pairwise distances
__device__ int   g_knn[BN_ * K_];                 // global neighbor indices
__device__ float g_ab[(size_t)BN_ * 672];         // per-node a (0..335) and b (336..671)
__device__ float g_wcomb[256 * 672];              // combined first-linear weights
__device__ float g_bcomb[672];
__device__ float g_cat[(size_t)BN_ * CAT_];       // concat features
__device__ float g_t[(size_t)BN_ * H_];           // mlp1 hidden
__device__ float g_m[(size_t)BN_ * C_];           // mlp1 output per node
__device__ float g_norm[BN_];
__device__ float g_pool[B_ * C_];

__device__ __forceinline__ float lrelu(float v) { return v >= 0.f ? v : 0.01f * v; }

// ---------------- small kernels ----------------

__global__ void norm_kernel(const float* __restrict__ x, float* __restrict__ nrm, int F) {
    int i = blockIdx.x * blockDim.x + threadIdx.x;
    if (i >= BN_) return;
    const float* r = x + (size_t)i * F;
    float s = 0.f;
    for (int f = 0; f < F; ++f) { float v = r[f]; s += v * v; }
    nrm[i] = s;
}

// Top-8 smallest distances per row; ties -> smaller index.
__global__ void topk_kernel(const float* __restrict__ D, int* __restrict__ knn) {
    int gid = blockIdx.x * blockDim.x + threadIdx.x;
    if (gid >= BN_) return;
    const float* row = D + (size_t)gid * N_;
    float kd[K_];
    int ki[K_];
#pragma unroll
    for (int k = 0; k < K_; ++k) { kd[k] = FLT_MAX; ki[k] = -1; }
    for (int j = 0; j < N_; ++j) {
        float d = row[j];
        if (d < kd[K_ - 1]) {
            int p = K_ - 1;
            while (p > 0 && kd[p - 1] > d) { kd[p] = kd[p - 1]; ki[p] = ki[p - 1]; --p; }
            kd[p] = d;
            ki[p] = j;
        }
    }
    int b = gid / N_;
#pragma unroll
    for (int k = 0; k < K_; ++k) knn[gid * K_ + k] = b * N_ + ki[k];
}

// Combined first-linear weights: cols 0..335 = w1_top - w1_bot, cols 336..671 = w1_bot.
__global__ void prep_kernel(const float* __restrict__ w1, const float* __restrict__ b1,
                            float* __restrict__ wcomb, float* __restrict__ bcomb, int F) {
    int idx = blockIdx.x * blockDim.x + threadIdx.x;
    if (idx < 672) bcomb[idx] = (idx < H_) ? b1[idx] : 0.f;
    int total = F * 672;
    if (idx >= total) return;
    int f = idx / 672, h = idx % 672;
    float v;
    if (h < H_) v = w1[f * H_ + h] - w1[(F + f) * H_ + h];
    else        v = w1[(F + f) * H_ + (h - H_)];
    wcomb[idx] = v;
}

__global__ void concat_kernel(const float* __restrict__ x, const float* __restrict__ x1,
                              const float* __restrict__ x2, const float* __restrict__ x3,
                              const float* __restrict__ x4, float* __restrict__ cat) {
    int idx = blockIdx.x * blockDim.x + threadIdx.x;
    if (idx >= BN_ * CAT_) return;
    int i = idx / CAT_, f = idx % CAT_;
    float v;
    if (f < 6) {
        v = x[i * 6 + f];
    } else {
        int g = f - 6;
        int l = g >> 8, c = g & 255;
        const float* src = (l == 0) ? x1 : (l == 1) ? x2 : (l == 2) ? x3 : x4;
        v = src[(size_t)i * C_ + c];
    }
    cat[idx] = v;
}

__global__ void pool_kernel(const float* __restrict__ m, float* __restrict__ g) {
    int b = blockIdx.x, c = threadIdx.x;  // 256 threads
    float s = 0.f;
    for (int n = 0; n < N_; ++n) s += m[(size_t)(b * N_ + n) * C_ + c];
    g[b * C_ + c] = s * (1.f / (float)N_);
}

__global__ void head_kernel(const float* __restrict__ g, const float* __restrict__ w1,
                            const float* __restrict__ b1, const float* __restrict__ w2,
                            const float* __restrict__ b2, float* __restrict__ out) {
    __shared__ float sg[256];
    __shared__ float sh[128];
    int b = blockIdx.x, t = threadIdx.x;  // 128 threads
    sg[t] = g[b * 256 + t];
    sg[t + 128] = g[b * 256 + 128 + t];
    __syncthreads();
    float s = b1[t];
    for (int f = 0; f < 256; ++f) s += sg[f] * w1[f * 128 + t];
    sh[t] = lrelu(s);
    __syncthreads();
    if (t < 3) {
        float o = b2[t];
        for (int c = 0; c < 128; ++c) o += sh[c] * w2[c * 3 + t];
        out[b * 3 + t] = o;
    }
}

// ---------------- 128x128 double-buffered SGEMM ----------------
// C = act(A[M,K] @ W[K,N] + bias). 256 threads, 8x8 per thread, K-panel 8.
// GATHER: A rows are edges; A[e][k] = lrelu(ab[i][k] + ab[j][336+k]), i=e>>3, j=knn[e].
// MAXRED: epilogue reduces max over the 8 edge-rows of each node, applies bias+lrelu,
//         writes per-node output [node][256]. Requires N tile fully valid (N=256).
template <int GATHER, int ACT, int MAXRED>
__global__ __launch_bounds__(256, 2)
void gemm128(const float* __restrict__ A, const int* __restrict__ knn,
             const float* __restrict__ W, const float* __restrict__ bias,
             float* __restrict__ Cout, int M, int K, int N) {
    __shared__ float sA[2][8][128];
    __shared__ float sB[2][8][128];
    const int m0 = blockIdx.y * 128, n0 = blockIdx.x * 128;
    const int tid = threadIdx.x;
    const int tx = tid & 15, ty = tid >> 4;
    const int aRow = tid >> 1, aK = (tid & 1) * 4;
    const int bK = tid >> 5, bN = (tid & 31) * 4;

    const float* aP0;
    const float* aP1 = nullptr;
    if (GATHER) {
        int e = m0 + aRow;
        int i = e >> 3;
        int j = __ldg(&knn[e]);
        aP0 = A + (size_t)i * 672;
        aP1 = A + (size_t)j * 672 + 336;
    } else {
        aP0 = A + (size_t)(m0 + aRow) * K;
    }
    const bool k4 = ((K & 3) == 0);

    float acc[8][8];
#pragma unroll
    for (int r = 0; r < 8; ++r)
#pragma unroll
        for (int c = 0; c < 8; ++c) acc[r][c] = 0.f;

    const int nPanels = (K + 7) >> 3;
    float4 va, vb;

    auto loadPanel = [&](int k0) {
        int k = k0 + aK;
        if (GATHER) {
            if (k + 3 < K) {
                float4 u = *reinterpret_cast<const float4*>(aP0 + k);
                float4 v = *reinterpret_cast<const float4*>(aP1 + k);
                va.x = lrelu(u.x + v.x); va.y = lrelu(u.y + v.y);
                va.z = lrelu(u.z + v.z); va.w = lrelu(u.w + v.w);
            } else {
                float t[4];
#pragma unroll
                for (int q = 0; q < 4; ++q)
                    t[q] = (k + q < K) ? lrelu(aP0[k + q] + aP1[k + q]) : 0.f;
                va = make_float4(t[0], t[1], t[2], t[3]);
            }
        } else {
            if (k4 && k + 3 < K) {
                va = *reinterpret_cast<const float4*>(aP0 + k);
            } else {
                float t[4];
#pragma unroll
                for (int q = 0; q < 4; ++q) t[q] = (k + q < K) ? aP0[k + q] : 0.f;
                va = make_float4(t[0], t[1], t[2], t[3]);
            }
        }
        int kb = k0 + bK;
        if (kb < K && n0 + bN < N)
            vb = *reinterpret_cast<const float4*>(W + (size_t)kb * N + n0 + bN);
        else
            vb = make_float4(0.f, 0.f, 0.f, 0.f);
    };
    auto stsPanel = [&](int buf) {
        sA[buf][aK + 0][aRow] = va.x;
        sA[buf][aK + 1][aRow] = va.y;
        sA[buf][aK + 2][aRow] = va.z;
        sA[buf][aK + 3][aRow] = va.w;
        *reinterpret_cast<float4*>(&sB[buf][bK][bN]) = vb;
    };

    loadPanel(0);
    stsPanel(0);
    __syncthreads();
    int buf = 0;
    for (int p = 0; p < nPanels; ++p) {
        if (p + 1 < nPanels) loadPanel((p + 1) << 3);
#pragma unroll
        for (int k = 0; k < 8; ++k) {
            float4 a0 = *reinterpret_cast<const float4*>(&sA[buf][k][ty * 4]);
            float4 a1 = *reinterpret_cast<const float4*>(&sA[buf][k][ty * 4 + 64]);
            float4 b0 = *reinterpret_cast<const float4*>(&sB[buf][k][tx * 4]);
            float4 b1 = *reinterpret_cast<const float4*>(&sB[buf][k][tx * 4 + 64]);
            float ra[8] = {a0.x, a0.y, a0.z, a0.w, a1.x, a1.y, a1.z, a1.w};
            float rb[8] = {b0.x, b0.y, b0.z, b0.w, b1.x, b1.y, b1.z, b1.w};
#pragma unroll
            for (int r = 0; r < 8; ++r)
#pragma unroll
                for (int c = 0; c < 8; ++c) acc[r][c] = fmaf(ra[r], rb[c], acc[r][c]);
        }
        if (p + 1 < nPanels) stsPanel(buf ^ 1);
        __syncthreads();
        buf ^= 1;
    }

    if (MAXRED) {
        // Rows ty*4..ty*4+3 (+ partner ty^1 for +4..+7) form one node (8 edges).
#pragma unroll
        for (int c = 0; c < 8; ++c) {
            float vlo = fmaxf(fmaxf(acc[0][c], acc[1][c]), fmaxf(acc[2][c], acc[3][c]));
            float vhi = fmaxf(fmaxf(acc[4][c], acc[5][c]), fmaxf(acc[6][c], acc[7][c]));
            vlo = fmaxf(vlo, __shfl_xor_sync(0xffffffffu, vlo, 16));
            vhi = fmaxf(vhi, __shfl_xor_sync(0xffffffffu, vhi, 16));
            if ((ty & 1) == 0) {
                int n = n0 + ((c < 4) ? tx * 4 + c : 64 + tx * 4 + (c - 4));
                float bv = bias[n];
                int nodeLo = (m0 + ty * 4) >> 3;
                int nodeHi = (m0 + 64 + ty * 4) >> 3;
                Cout[(size_t)nodeLo * 256 + n] = lrelu(vlo + bv);
                Cout[(size_t)nodeHi * 256 + n] = lrelu(vhi + bv);
            }
        }
    } else {
#pragma unroll
        for (int r = 0; r < 8; ++r) {
            int m = m0 + ((r < 4) ? ty * 4 + r : 64 + ty * 4 + (r - 4));
            if (m >= M) continue;
#pragma unroll
            for (int cg = 0; cg < 2; ++cg) {
                int n = n0 + tx * 4 + cg * 64;
                if (n < N) {
                    float4 o;
                    o.x = acc[(r)][cg * 4 + 0] + (bias ? bias[n + 0] : 0.f);
                    o.y = acc[(r)][cg * 4 + 1] + (bias ? bias[n + 1] : 0.f);
                    o.z = acc[(r)][cg * 4 + 2] + (bias ? bias[n + 2] : 0.f);
                    o.w = acc[(r)][cg * 4 + 3] + (bias ? bias[n + 3] : 0.f);
                    if (ACT) { o.x = lrelu(o.x); o.y = lrelu(o.y); o.z = lrelu(o.z); o.w = lrelu(o.w); }
                    *reinterpret_cast<float4*>(&Cout[(size_t)m * N + n]) = o;
                }
            }
        }
    }
}

// ---------------- 128x128 double-buffered distance GEMM ----------------
// D[b][i][j] = |xi|^2 + |xj|^2 - 2 xi.xj
__global__ __launch_bounds__(256, 2)
void dist128(const float* __restrict__ X, const float* __restrict__ nrm,
             float* __restrict__ D, int F) {
    __shared__ float sA[2][8][128];
    __shared__ float sB[2][8][128];
    const int b = blockIdx.z;
    const int base = b * N_;
    const int i0 = blockIdx.y * 128, j0 = blockIdx.x * 128;
    const int tid = threadIdx.x;
    const int tx = tid & 15, ty = tid >> 4;
    const int aRow = tid >> 1, aK = (tid & 1) * 4;
    const float* pI = X + (size_t)(base + i0 + aRow) * F;
    const float* pJ = X + (size_t)(base + j0 + aRow) * F;
    const bool f4 = ((F & 3) == 0);

    float acc[8][8];
#pragma unroll
    for (int r = 0; r < 8; ++r)
#pragma unroll
        for (int c = 0; c < 8; ++c) acc[r][c] = 0.f;

    const int nPanels = (F + 7) >> 3;
    float4 va, vb;
    auto loadPanel = [&](int k0) {
        int k = k0 + aK;
        if (f4 && k + 3 < F) {
            va = *reinterpret_cast<const float4*>(pI + k);
            vb = *reinterpret_cast<const float4*>(pJ + k);
        } else {
            float ti[4], tj[4];
#pragma unroll
            for (int q = 0; q < 4; ++q) {
                ti[q] = (k + q < F) ? pI[k + q] : 0.f;
                tj[q] = (k + q < F) ? pJ[k + q] : 0.f;
            }
            va = make_float4(ti[0], ti[1], ti[2], ti[3]);
            vb = make_float4(tj[0], tj[1], tj[2], tj[3]);
        }
    };
    auto stsPanel = [&](int buf) {
        sA[buf][aK + 0][aRow] = va.x;
        sA[buf][aK + 1][aRow] = va.y;
        sA[buf][aK + 2][aRow] = va.z;
        sA[buf][aK + 3][aRow] = va.w;
        sB[buf][aK + 0][aRow] = vb.x;
        sB[buf][aK + 1][aRow] = vb.y;
        sB[buf][aK + 2][aRow] = vb.z;
        sB[buf][aK + 3][aRow] = vb.w;
    };

    loadPanel(0);
    stsPanel(0);
    __syncthreads();
    int buf = 0;
    for (int p = 0; p < nPanels; ++p) {
        if (p + 1 < nPanels) loadPanel((p + 1) << 3);
#pragma unroll
        for (int k = 0; k < 8; ++k) {
            float4 a0 = *reinterpret_cast<const float4*>(&sA[buf][k][ty * 4]);
            float4 a1 = *reinterpret_cast<const float4*>(&sA[buf][k][ty * 4 + 64]);
            float4 b0 = *reinterpret_cast<const float4*>(&sB[buf][k][tx * 4]);
            float4 b1 = *reinterpret_cast<const float4*>(&sB[buf][k][tx * 4 + 64]);
            float ra[8] = {a0.x, a0.y, a0.z, a0.w, a1.x, a1.y, a1.z, a1.w};
            float rb[8] = {b0.x, b0.y, b0.z, b0.w, b1.x, b1.y, b1.z, b1.w};
#pragma unroll
            for (int r = 0; r < 8; ++r)
#pragma unroll
                for (int c = 0; c < 8; ++c) acc[r][c] = fmaf(ra[r], rb[c], acc[r][c]);
        }
        if (p + 1 < nPanels) stsPanel(buf ^ 1);
        __syncthreads();
        buf ^= 1;
    }

#pragma unroll
    for (int r = 0; r < 8; ++r) {
        int i = i0 + ((r < 4) ? ty * 4 + r : 64 + ty * 4 + (r - 4));
        float ni = nrm[base + i];
#pragma unroll
        for (int cg = 0; cg < 2; ++cg) {
            int j = j0 + tx * 4 + cg * 64;
            float4 o;
            o.x = ni + nrm[base + j + 0] - 2.f * acc[r][cg * 4 + 0];
            o.y = ni + nrm[base + j + 1] - 2.f * acc[r][cg * 4 + 1];
            o.z = ni + nrm[base + j + 2] - 2.f * acc[r][cg * 4 + 2];
            o.w = ni + nrm[base + j + 3] - 2.f * acc[r][cg * 4 + 3];
            *reinterpret_cast<float4*>(&D[(size_t)(base + i) * N_ + j]) = o;
        }
    }
}

// ---------------- host ----------------
extern "C" void kernel_launch(void* const* d_in, const int* in_sizes, int n_in,
                              void* d_out, int out_size) {
    const float* x = (const float*)d_in[0];
    const float *cw1[4], *cb1[4], *cw2[4], *cb2[4];
    for (int L = 0; L < 4; ++L) {
        cw1[L] = (const float*)d_in[3 + 4 * L];
        cb1[L] = (const float*)d_in[4 + 4 * L];
        cw2[L] = (const float*)d_in[5 + 4 * L];
        cb2[L] = (const float*)d_in[6 + 4 * L];
    }
    const float* m1w1 = (const float*)d_in[19];
    const float* m1b1 = (const float*)d_in[20];
    const float* m1w2 = (const float*)d_in[21];
    const float* m1b2 = (const float*)d_in[22];
    const float* m2w1 = (const float*)d_in[23];
    const float* m2b1 = (const float*)d_in[24];
    const float* m2w2 = (const float*)d_in[25];
    const float* m2b2 = (const float*)d_in[26];
    float* out = (float*)d_out;

    float *p_xo, *p_d, *p_ab, *p_wc, *p_bc, *p_cat, *p_t, *p_m, *p_nrm, *p_pool;
    int* p_knn;
    cudaGetSymbolAddress((void**)&p_xo, g_xo);
    cudaGetSymbolAddress((void**)&p_d, g_dist);
    cudaGetSymbolAddress((void**)&p_knn, g_knn);
    cudaGetSymbolAddress((void**)&p_ab, g_ab);
    cudaGetSymbolAddress((void**)&p_wc, g_wcomb);
    cudaGetSymbolAddress((void**)&p_bc, g_bcomb);
    cudaGetSymbolAddress((void**)&p_cat, g_cat);
    cudaGetSymbolAddress((void**)&p_t, g_t);
    cudaGetSymbolAddress((void**)&p_m, g_m);
    cudaGetSymbolAddress((void**)&p_nrm, g_norm);
    cudaGetSymbolAddress((void**)&p_pool, g_pool);

    float* xL[4];
    for (int L = 0; L < 4; ++L) xL[L] = p_xo + (size_t)L * BN_ * C_;

    for (int L = 0; L < 4; ++L) {
        const float* xin = (L == 0) ? x : xL[L - 1];
        int F = (L == 0) ? 6 : C_;

        norm_kernel<<<BN_ / 256, 256>>>(xin, p_nrm, F);
        dist128<<<dim3(4, 4, B_), 256>>>(xin, p_nrm, p_d, F);
        topk_kernel<<<BN_ / 256, 256>>>(p_d, p_knn);
        prep_kernel<<<(F * 672 + 255) / 256, 256>>>(cw1[L], cb1[L], p_wc, p_bc, F);
        // per-node a|b : [BN, F] @ [F, 672]
        gemm128<0, 0, 0><<<dim3(6, BN_ / 128), 256>>>(xin, nullptr, p_wc, p_bc, p_ab,
                                                      BN_, F, 672);
        // fused edge gemm: gather lrelu(a_i + b_j), [BN*K,336]@[336,256], max over K, lrelu
        gemm128<1, 0, 1><<<dim3(2, (BN_ * K_) / 128), 256>>>(p_ab, p_knn, cw2[L], cb2[L],
                                                             xL[L], BN_ * K_, H_, C_);
    }

    concat_kernel<<<(BN_ * CAT_ + 255) / 256, 256>>>(x, xL[0], xL[1], xL[2], xL[3], p_cat);
    gemm128<0, 1, 0><<<dim3(3, BN_ / 128), 256>>>(p_cat, nullptr, m1w1, m1b1, p_t,
                                                  BN_, CAT_, H_);
    gemm128<0, 1, 0><<<dim3(2, BN_ / 128), 256>>>(p_t, nullptr, m1w2, m1b2, p_m,
                                                  BN_, H_, C_);
    pool_kernel<<<B_, 256>>>(p_m, p_pool);
    head_kernel<<<B_, 128>>>(p_pool, m2w1, m2b1, m2w2, m2b2, out);
}